// round 1
// baseline (speedup 1.0000x reference)
#include <cuda_runtime.h>

// out[r] = W[0] + b[0] + sum_i W[1+i]*x[r,i] + sum_{i<=j} W[65+k]*x[r,i]*x[r,j]
// Fold linear weight into the triangular row sum:
//   s_i = W[1+i] + sum_{j>=i} Wq[i][j] * x_j ;  acc += x_i * s_i
// ~2144 FFMA per row; W broadcast from shared; x row in registers.

#define NPOLY 2145
#define DIMS  64
#define NROWS 32768
#define TPB   256
#define GRID  148

__global__ void __launch_bounds__(TPB, 1)
poly_model_kernel(const float* __restrict__ x,
                  const float* __restrict__ W,
                  const float* __restrict__ bias,
                  float* __restrict__ out)
{
    __shared__ float ws[NPOLY];
    const int tid = threadIdx.x;

    // Stage all weights into shared (L2-resident source, tiny).
    #pragma unroll
    for (int k = tid; k < NPOLY; k += TPB) ws[k] = W[k];
    __syncthreads();

    // Balanced strided row mapping: each SM's block handles ~221 rows.
    const int row = tid * (int)gridDim.x + (int)blockIdx.x;
    if (row >= NROWS) return;

    // Load the row into registers (16 x float4).
    float xr[DIMS];
    const float4* xp = reinterpret_cast<const float4*>(x + (long)row * DIMS);
    #pragma unroll
    for (int q = 0; q < DIMS / 4; q++) {
        float4 v = xp[q];
        xr[4*q + 0] = v.x;
        xr[4*q + 1] = v.y;
        xr[4*q + 2] = v.z;
        xr[4*q + 3] = v.w;
    }

    float acc = ws[0] + bias[0];

    #pragma unroll
    for (int i = 0; i < DIMS; i++) {
        // start of quadratic row i in W: 65 + 64*i - i*(i-1)/2
        const int base = 1 + DIMS + DIMS * i - (i * (i - 1)) / 2;
        float s = ws[1 + i];                 // linear weight folded in
        #pragma unroll
        for (int j = i; j < DIMS; j++) {
            s = fmaf(ws[base + (j - i)], xr[j], s);
        }
        acc = fmaf(xr[i], s, acc);
    }

    out[row] = acc;
}

extern "C" void kernel_launch(void* const* d_in, const int* in_sizes, int n_in,
                              void* d_out, int out_size)
{
    const float* x    = (const float*)d_in[0];  // [32768, 64]
    const float* W    = (const float*)d_in[1];  // [2145]
    const float* bias = (const float*)d_in[2];  // [1]
    float* out = (float*)d_out;                 // [32768]

    poly_model_kernel<<<GRID, TPB>>>(x, W, bias, out);
}